// round 10
// baseline (speedup 1.0000x reference)
#include <cuda_runtime.h>
#include <cuda_bf16.h>
#include <math_constants.h>

// Problem constants (fixed by the benchmark)
#define BB 2
#define LL 2048
#define HH 8
#define DD 64
#define UU 80
#define SS 80
#define BHN (BB*HH)
#define SPLIT 16
#define CHUNK (LL/SPLIT)      // 128 keys per split block
#define UST 8                 // u-stride for winner loop

// Sample kernel tiling
#define LT 256                // l rows per CTA (one per thread-pair)
#define NKT 8                 // key tiles
#define KT 256                // keys per tile
#define BLKS_PER_BH (LL/LT)   // 8 sample CTAs per (b,h)
// dynamic smem: Ks 64KB + sjb 20KB + soff 2.25KB
#define SMP_SMEM (KT*DD*4 + LT*SS + LT*(NKT+1))

// Scratch (device globals; zero-initialized at module load)
__device__ float g_M[BB*HH*LL];           // sparsity measure M[b,h,l]
__device__ float g_vmean[BHN*DD];         // V column sums (atomic), re-zeroed after use
__device__ int   g_cb[BHN];               // per-bh completion counter (self-reset)
__device__ int   g_cu[BHN*UU];            // per-(bh,u) split counter (self-reset)
__device__ int   g_nw[BHN];               // winners per (b,h)
__device__ int   g_wl[BHN*UU];            // winner: source token l
__device__ int   g_wj[BHN*UU];            // winner: output slot j
__device__ float g_pmax[BHN*UU*SPLIT];    // split-softmax partial max
__device__ float g_psum[BHN*UU*SPLIT];    // split-softmax partial sum(exp)
__device__ float g_pv  [BHN*UU*SPLIT*DD]; // split partial (unnormalized) PV

// ---------------------------------------------------------------------------
// Kernel 1: SMEM-crossbar-routed sampled scores + V sums + (last CTA per bh)
// top-80. CTA = 512 threads, 256 l rows. Thread pair (2k, 2k+1) owns l=k:
// lane parity = dim-half; Q half-row in registers; per-l max/sum in registers
// across all tiles; ONE shfl per sample joins the half-dots. K tiles staged
// (64KB, XOR-swizzled) and read via dense predicated LDS.128.
// ---------------------------------------------------------------------------
__global__ void __launch_bounds__(512, 1)
k_sample_topk(const float* __restrict__ Q, const float* __restrict__ K,
              const float* __restrict__ V, const int* __restrict__ idx,
              float* __restrict__ out) {
    extern __shared__ char dsm[];
    float* Ks = (float*)dsm;                                  // KT*DD floats
    unsigned char* sjb  = (unsigned char*)(dsm + KT*DD*4);    // LT*SS (tile-local j)
    unsigned char* soff = sjb + LT*SS;                        // LT*(NKT+1)

    __shared__ float vtmp[8][DD];
    __shared__ int   isLast;
    // top-k state (last block per bh only)
    __shared__ unsigned su[LL];
    __shared__ int hist[256];
    __shared__ int scnt2[2];
    __shared__ unsigned long long keys[128];
    __shared__ int eqbuf[256];
    __shared__ int cgt, ceq;
    __shared__ int stopA[UU];
    __shared__ int win[UU];
    __shared__ float meanS[DD];

    int t = threadIdx.x, lane = t & 31;
    int bh = blockIdx.y;
    int b = bh >> 3, h = bh & 7;
    int l0 = blockIdx.x * LT;
    int l = t >> 1, half = t & 1;

    // ---- V partial column sums for this l-tile (coalesced) ----
    {
        int rg = t >> 6, d = t & 63;
        float s = 0.f;
        #pragma unroll 8
        for (int lr = rg; lr < LT; lr += 8)
            s += V[(((size_t)b*LL + l0 + lr)*HH + h)*DD + d];
        vtmp[rg][d] = s;
    }

    // ---- bucket build: thread t<LT owns row l0+t, counting-sorts its 80
    //      samples by key tile (validated R7 pattern; tile-local j in u8) ----
    if (t < LT) {
        const int4* ir = (const int4*)(idx + (size_t)(l0 + t)*SS);
        int c[NKT];
        #pragma unroll
        for (int i = 0; i < NKT; ++i) c[i] = 0;
        #pragma unroll 5
        for (int q4 = 0; q4 < SS/4; ++q4) {
            int4 v = ir[q4];
            c[v.x >> 8]++; c[v.y >> 8]++; c[v.z >> 8]++; c[v.w >> 8]++;
        }
        int off[NKT+1]; off[0] = 0;
        #pragma unroll
        for (int i = 0; i < NKT; ++i) off[i+1] = off[i] + c[i];
        #pragma unroll
        for (int i = 0; i <= NKT; ++i) soff[t*(NKT+1) + i] = (unsigned char)off[i];
        int cur[NKT];
        #pragma unroll
        for (int i = 0; i < NKT; ++i) cur[i] = off[i];
        #pragma unroll 5
        for (int q4 = 0; q4 < SS/4; ++q4) {
            int4 v = ir[q4];
            sjb[t*SS + cur[v.x >> 8]++] = (unsigned char)(v.x & 255);
            sjb[t*SS + cur[v.y >> 8]++] = (unsigned char)(v.y & 255);
            sjb[t*SS + cur[v.z >> 8]++] = (unsigned char)(v.z & 255);
            sjb[t*SS + cur[v.w >> 8]++] = (unsigned char)(v.w & 255);
        }
    }

    // finish V sums (one atomic per d)
    __syncthreads();
    if (t < DD) {
        float s = 0.f;
        #pragma unroll
        for (int i = 0; i < 8; ++i) s += vtmp[i][t];
        atomicAdd(&g_vmean[bh*DD + t], s);
    }

    // ---- Q half-row into registers (one-time, coalesced 128B chunks) ----
    float4 qv[8];
    {
        const float4* qp = (const float4*)(Q + (((size_t)b*LL + l0 + l)*HH + h)*DD) + half*8;
        #pragma unroll
        for (int i = 0; i < 8; ++i) qv[i] = qp[i];
    }

    float vmax = -CUDART_INF_F, vsum = 0.f;

    // ---- main loop over key tiles ----
    for (int kt = 0; kt < NKT; ++kt) {
        // stage K tile with XOR swizzle (row-dependent float4 rotation)
        #pragma unroll
        for (int e = t; e < KT*16; e += 512) {
            int row = e >> 4, d4 = e & 15;
            float4 v = *((const float4*)(K + (((size_t)b*LL + kt*KT + row)*HH + h)*DD) + d4);
            ((float4*)Ks)[row*16 + (d4 ^ (row & 7))] = v;
        }
        __syncthreads();

        int s0 = soff[l*(NKT+1) + kt];
        int n  = soff[l*(NKT+1) + kt + 1] - s0;
        int nmax = n;
        #pragma unroll
        for (int o = 16; o; o >>= 1)
            nmax = max(nmax, __shfl_xor_sync(0xffffffffu, nmax, o));

        for (int it = 0; it < nmax; ++it) {
            bool ok = it < n;
            int jrow = ok ? (int)sjb[l*SS + s0 + it] : 0;   // inactive -> row 0 (broadcast)
            const float4* kb = (const float4*)Ks + jrow*16 + half*8;
            int sw = jrow & 7;
            float a0 = 0.f, a1 = 0.f, a2 = 0.f, a3 = 0.f;
            #pragma unroll
            for (int i = 0; i < 8; ++i) {
                float4 kv = kb[i ^ sw];
                float4 qq = qv[i];
                a0 = fmaf(qq.x, kv.x, a0);
                a1 = fmaf(qq.y, kv.y, a1);
                a2 = fmaf(qq.z, kv.z, a2);
                a3 = fmaf(qq.w, kv.w, a3);
            }
            float mine = (a0 + a1) + (a2 + a3);
            float full = mine + __shfl_xor_sync(0xffffffffu, mine, 1);
            if (ok) { vmax = fmaxf(vmax, full); vsum += full; }
        }
        __syncthreads();   // before next tile overwrites Ks
    }

    if (half == 0)
        g_M[bh*LL + l0 + l] = vmax - vsum * (1.0f/(float)LL);

    // ---- completion protocol: last block of this bh runs top-k inline ----
    __threadfence();
    __syncthreads();
    if (t == 0) {
        int old = atomicAdd(&g_cb[bh], 1);
        isLast = (old == BLKS_PER_BH - 1);
    }
    __syncthreads();
    if (!isLast) return;
    if (t == 0) g_cb[bh] = 0;                  // self-reset for next replay

    // ======================= top-k body (last block) =======================
    if (t < DD) {
        meanS[t] = g_vmean[bh*DD + t] * (1.0f/(float)LL);
        g_vmean[bh*DD + t] = 0.f;
    }
    for (int i = t; i < LL; i += 512) {
        unsigned bb = __float_as_uint(g_M[bh*LL + i]);
        su[i] = (bb & 0x80000000u) ? ~bb : (bb | 0x80000000u);
    }
    __syncthreads();

    // broadcast-fill all 80 output rows with V_mean (winners overwritten later)
    for (int e = t; e < UU*DD; e += 512) {
        int j = e >> 6, d = e & 63;
        out[(((size_t)b*UU + j)*HH + h)*DD + d] = meanS[d];
    }

    // 4-pass byte radix: T = 80th-largest transformed value
    unsigned prefix = 0, prefmask = 0;
    int need = UU;
    for (int pass = 0; pass < 4; ++pass) {
        int shift = 24 - pass*8;
        if (t < 256) hist[t] = 0;
        __syncthreads();
        for (int i = t; i < LL; i += 512) {
            unsigned u = su[i];
            if ((u & prefmask) == prefix) atomicAdd(&hist[(u >> shift) & 0xFF], 1);
        }
        __syncthreads();
        if (t < 32) {
            int base = 255 - t*8;
            int s = 0;
            #pragma unroll
            for (int e = 0; e < 8; ++e) s += hist[base - e];
            int pre = s;
            #pragma unroll
            for (int o = 1; o < 32; o <<= 1) {
                int v = __shfl_up_sync(0xffffffffu, pre, o);
                if (lane >= o) pre += v;
            }
            int excl = pre - s;
            if (excl < need && need <= pre) {
                int acc = excl;
                #pragma unroll
                for (int e = 0; e < 8; ++e) {
                    int hb = hist[base - e];
                    if (acc + hb >= need) { scnt2[0] = base - e; scnt2[1] = acc; break; }
                    acc += hb;
                }
            }
        }
        __syncthreads();
        prefix |= ((unsigned)scnt2[0]) << shift;
        prefmask |= 0xFFu << shift;
        need -= scnt2[1];
        __syncthreads();
    }
    unsigned T = prefix;

    if (t == 0) { cgt = 0; ceq = 0; }
    __syncthreads();
    for (int i = t; i < LL; i += 512) {
        unsigned u = su[i];
        if (u > T) {
            int p = atomicAdd(&cgt, 1);
            keys[p] = ((unsigned long long)u << 32) | (unsigned)(~i);
        } else if (u == T) {
            int p = atomicAdd(&ceq, 1);
            if (p < 256) eqbuf[p] = i;
        }
    }
    __syncthreads();
    if (t == 0) {
        int base = cgt;
        int ce = min(ceq, 256);
        for (int k = 0; k < need; ++k) {
            int mi = 0x7fffffff, mp = -1;
            for (int e = 0; e < ce; ++e)
                if (eqbuf[e] < mi) { mi = eqbuf[e]; mp = e; }
            keys[base + k] = ((unsigned long long)T << 32) | (unsigned)(~mi);
            eqbuf[mp] = 0x7fffffff;
        }
    }
    if (t < 128 && t >= UU) keys[t] = 0ULL;
    __syncthreads();

    // bitonic sort, 128 elements, descending (=> value desc, index asc)
    for (int ksz = 2; ksz <= 128; ksz <<= 1) {
        for (int jst = ksz >> 1; jst > 0; jst >>= 1) {
            __syncthreads();
            if (t < 128) {
                int ixj = t ^ jst;
                if (ixj > t) {
                    unsigned long long a = keys[t], cc = keys[ixj];
                    bool up = (t & ksz) == 0;
                    if (up ? (a < cc) : (a > cc)) { keys[t] = cc; keys[ixj] = a; }
                }
            }
        }
    }
    __syncthreads();

    if (t < UU) {
        stopA[t] = (int)(~(unsigned)(keys[t] & 0xffffffffu));
        win[t] = -1;
    }
    __syncthreads();
    if (t == 0) {
        for (int u = 0; u < UU; ++u) { int jj = min(stopA[u], UU-1); win[jj] = u; }
        int n2 = 0;
        for (int jj = 0; jj < UU; ++jj) {
            if (win[jj] >= 0) {
                g_wl[bh*UU + n2] = stopA[win[jj]];
                g_wj[bh*UU + n2] = jj;
                n2++;
            }
        }
        g_nw[bh] = n2;
    }
}

// ---------------------------------------------------------------------------
// Kernel 2: split-K attention partials for winner rows with last-split-block
// combine. SPLIT=16, CHUNK=128, 256 threads, grid (bh, UST, SPLIT).
// (Measured 18.9-19.5us across R6-R9 — verbatim.)
// ---------------------------------------------------------------------------
__global__ void k_attn(const float* __restrict__ Q, const float* __restrict__ K,
                       const float* __restrict__ V, float* __restrict__ out) {
    int bh = blockIdx.x;
    int n = g_nw[bh];
    int b = bh >> 3, h = bh & 7;
    int sp = blockIdx.z, k0 = sp * CHUNK;

    __shared__ float q[DD];
    __shared__ float p[CHUNK];
    __shared__ float red[8];
    __shared__ float ac[4][64];
    __shared__ int lastf;
    int t = threadIdx.x, lane = t & 31, warp = t >> 5;
    int grp = lane >> 3, lg = lane & 7;

    for (int u = blockIdx.y; u < n; u += UST) {
        int l = g_wl[bh*UU + u];
        if (t < DD) q[t] = Q[(((size_t)b*LL + l)*HH + h)*DD + t];
        __syncthreads();
        float4 q0 = ((float4*)q)[lg*2];
        float4 q1 = ((float4*)q)[lg*2 + 1];

        float lmax = -CUDART_INF_F;
        #pragma unroll
        for (int it = 0; it < 4; ++it) {
            int kk = warp*16 + it*4 + grp;
            const float* kr = K + (((size_t)b*LL + k0 + kk)*HH + h)*DD + lg*8;
            float4 k0v = *(const float4*)kr;
            float4 k1v = *(const float4*)(kr + 4);
            float s = q0.x*k0v.x + q0.y*k0v.y + q0.z*k0v.z + q0.w*k0v.w
                    + q1.x*k1v.x + q1.y*k1v.y + q1.z*k1v.z + q1.w*k1v.w;
            s += __shfl_xor_sync(0xffffffffu, s, 4);
            s += __shfl_xor_sync(0xffffffffu, s, 2);
            s += __shfl_xor_sync(0xffffffffu, s, 1);
            s *= 0.125f;                 // 1/sqrt(64)
            if (lg == 0) p[kk] = s;
            lmax = fmaxf(lmax, s);
        }
        lmax = fmaxf(lmax, __shfl_xor_sync(0xffffffffu, lmax, 8));
        lmax = fmaxf(lmax, __shfl_xor_sync(0xffffffffu, lmax, 16));
        if (lane == 0) red[warp] = lmax;
        __syncthreads();
        if (t == 0) { float m = red[0]; for (int w = 1; w < 8; ++w) m = fmaxf(m, red[w]); red[0] = m; }
        __syncthreads();
        float m = red[0];
        __syncthreads();

        float e = 0.f;
        if (t < CHUNK) { e = __expf(p[t] - m); p[t] = e; }
        float ls = e;
        #pragma unroll
        for (int o = 16; o; o >>= 1) ls += __shfl_xor_sync(0xffffffffu, ls, o);
        if (lane == 0) red[warp] = ls;
        __syncthreads();
        float ssumv = red[0]+red[1]+red[2]+red[3]+red[4]+red[5]+red[6]+red[7];

        int g4 = t >> 6, d = t & 63;
        float acc = 0.f;
        #pragma unroll 8
        for (int kk = g4; kk < CHUNK; kk += 4)
            acc += p[kk] * V[(((size_t)b*LL + k0 + kk)*HH + h)*DD + d];
        ac[g4][d] = acc;
        __syncthreads();
        int base = (bh*UU + u)*SPLIT + sp;
        if (t < 64)
            g_pv[(size_t)base*DD + t] = ac[0][t] + ac[1][t] + ac[2][t] + ac[3][t];
        if (t == 0) { g_pmax[base] = m; g_psum[base] = ssumv; }

        __threadfence();
        __syncthreads();
        if (t == 0) {
            int old = atomicAdd(&g_cu[bh*UU + u], 1);
            lastf = (old == SPLIT - 1);
        }
        __syncthreads();
        if (lastf) {
            if (t == 0) g_cu[bh*UU + u] = 0;   // self-reset for replay
            if (t < 64) {
                int cb = (bh*UU + u)*SPLIT;
                float mm = -CUDART_INF_F;
                #pragma unroll
                for (int i = 0; i < SPLIT; ++i) mm = fmaxf(mm, g_pmax[cb + i]);
                float s = 0.f, pv = 0.f;
                #pragma unroll
                for (int i = 0; i < SPLIT; ++i) {
                    float w = __expf(g_pmax[cb + i] - mm);
                    s  += g_psum[cb + i] * w;
                    pv += g_pv[(size_t)(cb + i)*DD + t] * w;
                }
                int j = g_wj[bh*UU + u];
                out[(((size_t)b*UU + j)*HH + h)*DD + t] = pv / s;
            }
        }
        __syncthreads();
    }
}

// ---------------------------------------------------------------------------
extern "C" void kernel_launch(void* const* d_in, const int* in_sizes, int n_in,
                              void* d_out, int out_size) {
    const float* Q   = (const float*)d_in[0];
    const float* K   = (const float*)d_in[1];
    const float* V   = (const float*)d_in[2];
    const int*   idx = (const int*)d_in[3];
    float* out = (float*)d_out;

    cudaFuncSetAttribute(k_sample_topk,
                         cudaFuncAttributeMaxDynamicSharedMemorySize, SMP_SMEM);

    dim3 gs(BLKS_PER_BH, BHN);
    k_sample_topk<<<gs, 512, SMP_SMEM>>>(Q, K, V, idx, out);
    dim3 ga(BHN, UST, SPLIT);
    k_attn<<<ga, 256>>>(Q, K, V, out);
}

// round 12
// speedup vs baseline: 1.0839x; 1.0839x over previous
#include <cuda_runtime.h>
#include <cuda_bf16.h>
#include <math_constants.h>

// Problem constants (fixed by the benchmark)
#define BB 2
#define LL 2048
#define HH 8
#define DD 64
#define UU 80
#define SS 80
#define BHN (BB*HH)
#define SPLIT 16
#define CHUNK (LL/SPLIT)      // 128 keys per attn split block
#define UST 8                 // u-stride for winner loop

// Sample-stage tiling
#define KT2 128               // keys per tile
#define NT2 (LL/KT2)          // 16 key tiles
#define NLS 8                 // l-slices for pair building (256 l each)
#define SEGCAP 3072           // pair capacity per (tile, l-slice); expected ~1280
#define KROW 68               // padded K row stride in floats (bank spread)
#define BLKS_PER_BH NT2       // 16 sample CTAs per (b,h)
#define SMP_DYN (KT2*KROW*4)  // 34816 B dynamic smem

// Scratch (device globals; zero-initialized at module load)
__device__ unsigned g_pairs[NT2*NLS*SEGCAP]; // (l<<7|jloc), sorted by l per segment
__device__ int      g_pcnt2[NT2*NLS];        // pairs per segment (rewritten each run)
__device__ unsigned g_MmaxU[BHN*LL];         // encoded per-l max (atomic; reset by topk)
__device__ float    g_Msum [BHN*LL];         // per-l sum (atomic; reset by topk)
__device__ float    g_vmean[BHN*DD];         // V column sums (atomic; reset by topk)
__device__ int      g_cb[BHN];               // per-bh completion counter (self-reset)
__device__ int      g_cu[BHN*UU];            // per-(bh,u) split counter (self-reset)
__device__ int      g_nw[BHN];               // winners per (b,h)
__device__ int      g_wl[BHN*UU];            // winner: source token l
__device__ int      g_wj[BHN*UU];            // winner: output slot j
__device__ float    g_pmax[BHN*UU*SPLIT];    // split-softmax partial max
__device__ float    g_psum[BHN*UU*SPLIT];    // split-softmax partial sum(exp)
__device__ float    g_pv  [BHN*UU*SPLIT*DD]; // split partial (unnormalized) PV

// monotone float<->uint order encoding (exact compares; 0 == "empty")
__device__ __forceinline__ unsigned fenc(float x) {
    unsigned b = __float_as_uint(x);
    return (b & 0x80000000u) ? ~b : (b | 0x80000000u);
}
__device__ __forceinline__ float fdec(unsigned u) {
    unsigned b = (u & 0x80000000u) ? (u & 0x7FFFFFFFu) : ~u;
    return __uint_as_float(b);
}

// ---------------------------------------------------------------------------
// Kernel 0: build dense l-sorted pair lists per (key-tile, l-slice).
// Shared across all (b,h). Deterministic positions via block scan.
// ---------------------------------------------------------------------------
__global__ void k_pairs(const int* __restrict__ idx) {
    int kt = blockIdx.x, ls = blockIdx.y;
    int t = threadIdx.x, lane = t & 31, warp = t >> 5;
    __shared__ int wsum[8];

    int l = ls*256 + t;
    const int* row = idx + l*SS;
    int c = 0;
    #pragma unroll 10
    for (int q = 0; q < SS; ++q) c += ((row[q] >> 7) == kt);

    // warp inclusive scan
    int pre = c;
    #pragma unroll
    for (int o = 1; o < 32; o <<= 1) {
        int v = __shfl_up_sync(0xffffffffu, pre, o);
        if (lane >= o) pre += v;
    }
    if (lane == 31) wsum[warp] = pre;
    __syncthreads();
    int wbase = 0;
    for (int w = 0; w < warp; ++w) wbase += wsum[w];
    int pos = wbase + pre - c;            // exclusive prefix = my start
    if (t == 255) g_pcnt2[kt*NLS + ls] = min(wbase + pre, SEGCAP);

    unsigned* seg = g_pairs + (kt*NLS + ls)*SEGCAP;
    #pragma unroll 10
    for (int q = 0; q < SS; ++q) {
        int j = row[q];
        if ((j >> 7) == kt) {
            if (pos < SEGCAP) seg[pos] = (unsigned)((l << 7) | (j & 127));
            pos++;
        }
    }
}

// ---------------------------------------------------------------------------
// Kernel 1: SMEM-crossbar sampled scores. CTA = (key-tile, bh), 256 threads.
// K tile (128 rows, stride-68) staged in smem. 32 eight-lane groups walk
// contiguous chunks of the dense l-sorted pair lists: per pair 1 LDG (pair,
// broadcast within group), 2 LDS.128 (K), 8 FFMA, 3-shfl butterfly; Q
// reloaded from L1 on l-change (l-sorted runs ~10); per-run register max/sum
// flushed to smem (encoded atomicMax / atomicAdd) on l-change only.
// Per-CTA export via global atomics; last CTA per bh runs the validated
// radix+bitonic top-80, winner replay, and V_mean fill.
// ---------------------------------------------------------------------------
__global__ void __launch_bounds__(256)
k_sample_topk(const float* __restrict__ Q, const float* __restrict__ K,
              const float* __restrict__ V, float* __restrict__ out) {
    extern __shared__ float Ks[];           // KT2*KROW floats (34.8KB)
    __shared__ unsigned smaxU[LL];          // per-l encoded max (8KB)
    __shared__ float    ssum[LL];           // per-l sum (8KB)
    __shared__ float    vtmp[4][DD];
    __shared__ int      isLast;
    // top-k state (last CTA per bh only)
    __shared__ unsigned su[LL];
    __shared__ int hist[256];
    __shared__ int scnt2[2];
    __shared__ unsigned long long keys[128];
    __shared__ int eqbuf[256];
    __shared__ int cgt, ceq;
    __shared__ int stopA[UU];
    __shared__ int win[UU];
    __shared__ float meanS[DD];

    int t = threadIdx.x, lane = t & 31;
    int kt = blockIdx.x, bh = blockIdx.y;
    int b = bh >> 3, h = bh & 7;
    int G = t >> 3, lg = t & 7;             // 32 groups of 8 lanes

    // zero per-l accumulators
    for (int i = t; i < LL; i += 256) { smaxU[i] = 0u; ssum[i] = 0.f; }

    // stage K tile (rows kt*128 .. +127), padded stride KROW
    #pragma unroll 8
    for (int e = t; e < KT2*16; e += 256) {
        int row = e >> 4, d4 = e & 15;
        float4 v = *((const float4*)(K + (((size_t)b*LL + kt*KT2 + row)*HH + h)*DD) + d4);
        *(float4*)(Ks + row*KROW + d4*4) = v;
    }

    // V partial sums for this CTA's 128-row slice
    {
        int rg = t >> 6, d = t & 63;
        float s = 0.f;
        #pragma unroll 8
        for (int lr = rg; lr < KT2; lr += 4)
            s += V[(((size_t)b*LL + kt*KT2 + lr)*HH + h)*DD + d];
        vtmp[rg][d] = s;
    }
    __syncthreads();
    if (t < DD)
        atomicAdd(&g_vmean[bh*DD + t], vtmp[0][t]+vtmp[1][t]+vtmp[2][t]+vtmp[3][t]);

    // ---- pair loop over the 8 l-slices of this tile ----
    int cur_l = -1;
    float rmax = -CUDART_INF_F, rsum = 0.f;
    float4 q0 = make_float4(0,0,0,0), q1 = q0;

    for (int seg = 0; seg < NLS; ++seg) {
        const unsigned* plist = g_pairs + (kt*NLS + seg)*SEGCAP;
        int npr = g_pcnt2[kt*NLS + seg];
        if (npr == 0) continue;
        int ch = (npr + 31) >> 5;           // chunk per group
        int s0 = G * ch;
        #pragma unroll 2
        for (int it = 0; it < ch; ++it) {
            int pidx = s0 + it;
            bool ok = pidx < npr;
            unsigned pv = plist[ok ? pidx : (npr - 1)];
            int l = pv >> 7, jl = pv & 127;
            if (l != cur_l) {               // uniform within the 8-lane group
                if (cur_l >= 0 && lg == 0) {
                    atomicMax(&smaxU[cur_l], fenc(rmax));
                    atomicAdd(&ssum[cur_l], rsum);
                }
                cur_l = l; rmax = -CUDART_INF_F; rsum = 0.f;
                const float4* qp = (const float4*)(Q + (((size_t)b*LL + l)*HH + h)*DD) + lg*2;
                q0 = qp[0]; q1 = qp[1];
            }
            const float* kb = Ks + jl*KROW + lg*8;
            float4 k0 = *(const float4*)kb;
            float4 k1 = *(const float4*)(kb + 4);
            float p = q0.x*k0.x + q0.y*k0.y + q0.z*k0.z + q0.w*k0.w
                    + q1.x*k1.x + q1.y*k1.y + q1.z*k1.z + q1.w*k1.w;
            p += __shfl_xor_sync(0xffffffffu, p, 4);
            p += __shfl_xor_sync(0xffffffffu, p, 2);
            p += __shfl_xor_sync(0xffffffffu, p, 1);
            if (ok) { rmax = fmaxf(rmax, p); rsum += p; }
        }
    }
    if (cur_l >= 0 && lg == 0) {            // final flush
        atomicMax(&smaxU[cur_l], fenc(rmax));
        atomicAdd(&ssum[cur_l], rsum);
    }
    __syncthreads();

    // export partials (only touched l's)
    for (int i = t; i < LL; i += 256) {
        unsigned mu = smaxU[i];
        if (mu) {
            atomicMax(&g_MmaxU[bh*LL + i], mu);
            atomicAdd(&g_Msum [bh*LL + i], ssum[i]);
        }
    }

    // ---- completion protocol: last CTA of this bh runs top-k inline ----
    __threadfence();
    __syncthreads();
    if (t == 0) {
        int old = atomicAdd(&g_cb[bh], 1);
        isLast = (old == BLKS_PER_BH - 1);
    }
    __syncthreads();
    if (!isLast) return;
    if (t == 0) g_cb[bh] = 0;               // self-reset for next replay

    // ======================= top-k body (last CTA) =========================
    if (t < DD) {
        meanS[t] = g_vmean[bh*DD + t] * (1.0f/(float)LL);
        g_vmean[bh*DD + t] = 0.f;
    }
    for (int i = t; i < LL; i += 256) {
        float M = fdec(g_MmaxU[bh*LL + i]) - g_Msum[bh*LL + i] * (1.0f/(float)LL);
        unsigned bb = __float_as_uint(M);
        su[i] = (bb & 0x80000000u) ? ~bb : (bb | 0x80000000u);
        g_MmaxU[bh*LL + i] = 0u;            // reset for replay
        g_Msum [bh*LL + i] = 0.f;
    }
    __syncthreads();

    // broadcast-fill all 80 output rows with V_mean (winners overwritten later)
    for (int e = t; e < UU*DD; e += 256) {
        int j = e >> 6, d = e & 63;
        out[(((size_t)b*UU + j)*HH + h)*DD + d] = meanS[d];
    }

    // 4-pass byte radix: T = 80th-largest transformed value
    unsigned prefix = 0, prefmask = 0;
    int need = UU;
    for (int pass = 0; pass < 4; ++pass) {
        int shift = 24 - pass*8;
        hist[t] = 0;
        __syncthreads();
        for (int i = t; i < LL; i += 256) {
            unsigned u = su[i];
            if ((u & prefmask) == prefix) atomicAdd(&hist[(u >> shift) & 0xFF], 1);
        }
        __syncthreads();
        if (t < 32) {
            int base = 255 - t*8;
            int s = 0;
            #pragma unroll
            for (int e = 0; e < 8; ++e) s += hist[base - e];
            int pre = s;
            #pragma unroll
            for (int o = 1; o < 32; o <<= 1) {
                int v = __shfl_up_sync(0xffffffffu, pre, o);
                if (lane >= o) pre += v;
            }
            int excl = pre - s;
            if (excl < need && need <= pre) {
                int acc = excl;
                #pragma unroll
                for (int e = 0; e < 8; ++e) {
                    int hb = hist[base - e];
                    if (acc + hb >= need) { scnt2[0] = base - e; scnt2[1] = acc; break; }
                    acc += hb;
                }
            }
        }
        __syncthreads();
        prefix |= ((unsigned)scnt2[0]) << shift;
        prefmask |= 0xFFu << shift;
        need -= scnt2[1];
        __syncthreads();
    }
    unsigned T = prefix;

    if (t == 0) { cgt = 0; ceq = 0; }
    __syncthreads();
    for (int i = t; i < LL; i += 256) {
        unsigned u = su[i];
        if (u > T) {
            int p = atomicAdd(&cgt, 1);
            keys[p] = ((unsigned long long)u << 32) | (unsigned)(~i);
        } else if (u == T) {
            int p = atomicAdd(&ceq, 1);
            if (p < 256) eqbuf[p] = i;
        }
    }
    __syncthreads();
    if (t == 0) {
        int base = cgt;
        int ce = min(ceq, 256);
        for (int k = 0; k < need; ++k) {
            int mi = 0x7fffffff, mp = -1;
            for (int e = 0; e < ce; ++e)
                if (eqbuf[e] < mi) { mi = eqbuf[e]; mp = e; }
            keys[base + k] = ((unsigned long long)T << 32) | (unsigned)(~mi);
            eqbuf[mp] = 0x7fffffff;
        }
    }
    for (int i = t; i < 128; i += 256) if (i >= UU) keys[i] = 0ULL;
    __syncthreads();

    // bitonic sort, 128 elements, descending (=> value desc, index asc)
    for (int ksz = 2; ksz <= 128; ksz <<= 1) {
        for (int jst = ksz >> 1; jst > 0; jst >>= 1) {
            __syncthreads();
            if (t < 128) {
                int ixj = t ^ jst;
                if (ixj > t) {
                    unsigned long long a = keys[t], cc = keys[ixj];
                    bool up = (t & ksz) == 0;
                    if (up ? (a < cc) : (a > cc)) { keys[t] = cc; keys[ixj] = a; }
                }
            }
        }
    }
    __syncthreads();

    if (t < UU) {
        stopA[t] = (int)(~(unsigned)(keys[t] & 0xffffffffu));
        win[t] = -1;
    }
    __syncthreads();
    if (t == 0) {
        for (int u = 0; u < UU; ++u) { int jj = min(stopA[u], UU-1); win[jj] = u; }
        int n2 = 0;
        for (int jj = 0; jj < UU; ++jj) {
            if (win[jj] >= 0) {
                g_wl[bh*UU + n2] = stopA[win[jj]];
                g_wj[bh*UU + n2] = jj;
                n2++;
            }
        }
        g_nw[bh] = n2;
    }
}

// ---------------------------------------------------------------------------
// Kernel 2: split-K attention partials for winner rows with last-split-block
// combine. SPLIT=16, CHUNK=128, 256 threads, grid (bh, UST, SPLIT).
// (Measured 18.9-19.5us across R6-R10 — verbatim.)
// ---------------------------------------------------------------------------
__global__ void k_attn(const float* __restrict__ Q, const float* __restrict__ K,
                       const float* __restrict__ V, float* __restrict__ out) {
    int bh = blockIdx.x;
    int n = g_nw[bh];
    int b = bh >> 3, h = bh & 7;
    int sp = blockIdx.z, k0 = sp * CHUNK;

    __shared__ float q[DD];
    __shared__ float p[CHUNK];
    __shared__ float red[8];
    __shared__ float ac[4][64];
    __shared__ int lastf;
    int t = threadIdx.x, lane = t & 31, warp = t >> 5;
    int grp = lane >> 3, lg = lane & 7;

    for (int u = blockIdx.y; u < n; u += UST) {
        int l = g_wl[bh*UU + u];
        if (t < DD) q[t] = Q[(((size_t)b*LL + l)*HH + h)*DD + t];
        __syncthreads();
        float4 q0 = ((float4*)q)[lg*2];
        float4 q1 = ((float4*)q)[lg*2 + 1];

        float lmax = -CUDART_INF_F;
        #pragma unroll
        for (int it = 0; it < 4; ++it) {
            int kk = warp*16 + it*4 + grp;
            const float* kr = K + (((size_t)b*LL + k0 + kk)*HH + h)*DD + lg*8;
            float4 k0v = *(const float4*)kr;
            float4 k1v = *(const float4*)(kr + 4);
            float s = q0.x*k0v.x + q0.y*k0v.y + q0.z*k0v.z + q0.w*k0v.w
                    + q1.x*k1v.x + q1.y*k1v.y + q1.z*k1v.z + q1.w*k1v.w;
            s += __shfl_xor_sync(0xffffffffu, s, 4);
            s += __shfl_xor_sync(0xffffffffu, s, 2);
            s += __shfl_xor_sync(0xffffffffu, s, 1);
            s *= 0.125f;                 // 1/sqrt(64)
            if (lg == 0) p[kk] = s;
            lmax = fmaxf(lmax, s);
        }
        lmax = fmaxf(lmax, __shfl_xor_sync(0xffffffffu, lmax, 8));
        lmax = fmaxf(lmax, __shfl_xor_sync(0xffffffffu, lmax, 16));
        if (lane == 0) red[warp] = lmax;
        __syncthreads();
        if (t == 0) { float m = red[0]; for (int w = 1; w < 8; ++w) m = fmaxf(m, red[w]); red[0] = m; }
        __syncthreads();
        float m = red[0];
        __syncthreads();

        float e = 0.f;
        if (t < CHUNK) { e = __expf(p[t] - m); p[t] = e; }
        float ls = e;
        #pragma unroll
        for (int o = 16; o; o >>= 1) ls += __shfl_xor_sync(0xffffffffu, ls, o);
        if (lane == 0) red[warp] = ls;
        __syncthreads();
        float ssumv = red[0]+red[1]+red[2]+red[3]+red[4]+red[5]+red[6]+red[7];

        int g4 = t >> 6, d = t & 63;
        float acc = 0.f;
        #pragma unroll 8
        for (int kk = g4; kk < CHUNK; kk += 4)
            acc += p[kk] * V[(((size_t)b*LL + k0 + kk)*HH + h)*DD + d];
        ac[g4][d] = acc;
        __syncthreads();
        int base = (bh*UU + u)*SPLIT + sp;
        if (t < 64)
            g_pv[(size_t)base*DD + t] = ac[0][t] + ac[1][t] + ac[2][t] + ac[3][t];
        if (t == 0) { g_pmax[base] = m; g_psum[base] = ssumv; }

        __threadfence();
        __syncthreads();
        if (t == 0) {
            int old = atomicAdd(&g_cu[bh*UU + u], 1);
            lastf = (old == SPLIT - 1);
        }
        __syncthreads();
        if (lastf) {
            if (t == 0) g_cu[bh*UU + u] = 0;   // self-reset for replay
            if (t < 64) {
                int cb = (bh*UU + u)*SPLIT;
                float mm = -CUDART_INF_F;
                #pragma unroll
                for (int i = 0; i < SPLIT; ++i) mm = fmaxf(mm, g_pmax[cb + i]);
                float s = 0.f, pv = 0.f;
                #pragma unroll
                for (int i = 0; i < SPLIT; ++i) {
                    float w = __expf(g_pmax[cb + i] - mm);
                    s  += g_psum[cb + i] * w;
                    pv += g_pv[(size_t)(cb + i)*DD + t] * w;
                }
                int j = g_wj[bh*UU + u];
                out[(((size_t)b*UU + j)*HH + h)*DD + t] = pv / s;
            }
        }
        __syncthreads();
    }
}

// ---------------------------------------------------------------------------
extern "C" void kernel_launch(void* const* d_in, const int* in_sizes, int n_in,
                              void* d_out, int out_size) {
    const float* Q   = (const float*)d_in[0];
    const float* K   = (const float*)d_in[1];
    const float* V   = (const float*)d_in[2];
    const int*   idx = (const int*)d_in[3];
    float* out = (float*)d_out;

    // REQUIRED: ~29.5KB static + 34.8KB dynamic smem exceeds the default
    // dynamic limit — R11 failed to launch without this.
    cudaFuncSetAttribute(k_sample_topk,
                         cudaFuncAttributeMaxDynamicSharedMemorySize, SMP_DYN);

    dim3 gp(NT2, NLS);
    k_pairs<<<gp, 256>>>(idx);
    dim3 gs(NT2, BHN);
    k_sample_topk<<<gs, 256, SMP_DYN>>>(Q, K, V, out);
    dim3 ga(BHN, UST, SPLIT);
    k_attn<<<ga, 256>>>(Q, K, V, out);
}

// round 13
// speedup vs baseline: 2.0461x; 1.8878x over previous
#include <cuda_runtime.h>
#include <cuda_bf16.h>
#include <math_constants.h>

// Problem constants (fixed by the benchmark)
#define BB 2
#define LL 2048
#define HH 8
#define DD 64
#define UU 80
#define SS 80
#define BHN (BB*HH)
#define SPLIT 16
#define CHUNK (LL/SPLIT)      // 128 keys per split block
#define UST 8                 // u-stride for winner loop
#define BLKS_PER_BH 256       // k_sample blocks per (b,h)

// Scratch (device globals; zero-initialized at module load)
__device__ float g_M[BB*HH*LL];           // sparsity measure M[b,h,l]
__device__ float g_vmean[BHN*DD];         // V column sums (atomic), re-zeroed after use
__device__ int   g_cb[BHN];               // per-bh completion counter (self-reset)
__device__ int   g_cu[BHN*UU];            // per-(bh,u) split counter (self-reset)
__device__ int   g_nw[BHN];               // winners per (b,h)
__device__ int   g_wl[BHN*UU];            // winner: source token l
__device__ int   g_wj[BHN*UU];            // winner: output slot j
__device__ float g_pmax[BHN*UU*SPLIT];    // split-softmax partial max
__device__ float g_psum[BHN*UU*SPLIT];    // split-softmax partial sum(exp)
__device__ float g_pv  [BHN*UU*SPLIT*DD]; // split partial (unnormalized) PV

// ---------------------------------------------------------------------------
// Kernel 1 (R5-validated, verbatim): sampled scores -> M[b,h,l] fused with V
// column sums; the LAST block of each (b,h) runs top-80 (radix select +
// bitonic, exact jax.lax.top_k semantics), winner replay, and V_mean fill.
// One warp per (b,h,l); 4 groups of 8 lanes, one sampled dot per group/iter
// (4 independent 256B LDG gathers in flight per warp-iteration).
// ---------------------------------------------------------------------------
__global__ void k_sample_topk(const float* __restrict__ Q, const float* __restrict__ K,
                              const float* __restrict__ V, const int* __restrict__ idx,
                              float* __restrict__ out) {
    __shared__ float sv[8][64];
    __shared__ int   isLast;
    // top-k shared state (only used by the last block per bh)
    __shared__ unsigned su[LL];
    __shared__ int hist[256];
    __shared__ int scnt[2];
    __shared__ unsigned long long keys[128];
    __shared__ int eqbuf[256];
    __shared__ int cgt, ceq;
    __shared__ int stop[UU];
    __shared__ int win[UU];
    __shared__ float mean[64];

    int t = threadIdx.x, lane = t & 31, warp = t >> 5;
    int gw = blockIdx.x * 8 + warp;
    int l  = gw & (LL-1);
    int bh = gw >> 11;
    int b = bh >> 3, h = bh & 7;
    int grp = lane >> 3, lg = lane & 7;

    const float* qrow = Q + (((size_t)b*LL + l)*HH + h)*DD;
    float4 q0 = *(const float4*)(qrow + lg*8);
    float4 q1 = *(const float4*)(qrow + lg*8 + 4);

    // V row for this l (coalesced float2 per lane)
    float2 vv = *(const float2*)(V + (((size_t)b*LL + l)*HH + h)*DD + lane*2);
    sv[warp][lane*2] = vv.x; sv[warp][lane*2+1] = vv.y;

    const int* irow = idx + l*SS;
    float vmax = -CUDART_INF_F, vsum = 0.f;

    #pragma unroll 5
    for (int it = 0; it < SS/4; ++it) {
        int j = irow[it*4 + grp];
        const float* krow = K + (((size_t)b*LL + j)*HH + h)*DD + lg*8;
        float4 k0 = *(const float4*)(krow);
        float4 k1 = *(const float4*)(krow + 4);
        float p = q0.x*k0.x + q0.y*k0.y + q0.z*k0.z + q0.w*k0.w
                + q1.x*k1.x + q1.y*k1.y + q1.z*k1.z + q1.w*k1.w;
        p += __shfl_xor_sync(0xffffffffu, p, 4);
        p += __shfl_xor_sync(0xffffffffu, p, 2);
        p += __shfl_xor_sync(0xffffffffu, p, 1);
        vmax = fmaxf(vmax, p);
        vsum += p;
    }
    vmax = fmaxf(vmax, __shfl_xor_sync(0xffffffffu, vmax, 8));
    vmax = fmaxf(vmax, __shfl_xor_sync(0xffffffffu, vmax, 16));
    vsum += __shfl_xor_sync(0xffffffffu, vsum, 8);
    vsum += __shfl_xor_sync(0xffffffffu, vsum, 16);
    if (lane == 0) g_M[gw] = vmax - vsum * (1.0f/(float)LL);

    __syncthreads();
    if (t < 64) {
        float s = sv[0][t] + sv[1][t] + sv[2][t] + sv[3][t]
                + sv[4][t] + sv[5][t] + sv[6][t] + sv[7][t];
        atomicAdd(&g_vmean[bh*64 + t], s);
    }

    // ---- completion protocol: last block of this bh runs top-k inline ----
    __threadfence();
    __syncthreads();
    if (t == 0) {
        int old = atomicAdd(&g_cb[bh], 1);
        isLast = (old == BLKS_PER_BH - 1);
    }
    __syncthreads();
    if (!isLast) return;
    if (t == 0) g_cb[bh] = 0;    // self-reset for next graph replay

    // ======================= top-k body (last block) =======================
    if (t < 64) {
        mean[t] = g_vmean[bh*64 + t] * (1.0f/(float)LL);
        g_vmean[bh*64 + t] = 0.f;
    }
    for (int i = t; i < LL; i += 256) {
        unsigned bb = __float_as_uint(g_M[bh*LL + i]);
        su[i] = (bb & 0x80000000u) ? ~bb : (bb | 0x80000000u);
    }
    __syncthreads();

    // broadcast-fill all 80 output rows with V_mean (winners overwritten later)
    for (int e = t; e < UU*64; e += 256) {
        int j = e >> 6, d = e & 63;
        out[(((size_t)b*UU + j)*HH + h)*DD + d] = mean[d];
    }

    // 4-pass byte radix: T = 80th-largest transformed value
    unsigned prefix = 0, prefmask = 0;
    int need = UU;
    for (int pass = 0; pass < 4; ++pass) {
        int shift = 24 - pass*8;
        hist[t] = 0;
        __syncthreads();
        for (int i = t; i < LL; i += 256) {
            unsigned u = su[i];
            if ((u & prefmask) == prefix) atomicAdd(&hist[(u >> shift) & 0xFF], 1);
        }
        __syncthreads();
        if (t < 32) {
            int base = 255 - t*8;
            int s = 0;
            #pragma unroll
            for (int e = 0; e < 8; ++e) s += hist[base - e];
            int pre = s;
            #pragma unroll
            for (int o = 1; o < 32; o <<= 1) {
                int v = __shfl_up_sync(0xffffffffu, pre, o);
                if (lane >= o) pre += v;
            }
            int excl = pre - s;
            if (excl < need && need <= pre) {
                int acc = excl;
                #pragma unroll
                for (int e = 0; e < 8; ++e) {
                    int hb = hist[base - e];
                    if (acc + hb >= need) { scnt[0] = base - e; scnt[1] = acc; break; }
                    acc += hb;
                }
            }
        }
        __syncthreads();
        prefix |= ((unsigned)scnt[0]) << shift;
        prefmask |= 0xFFu << shift;
        need -= scnt[1];
        __syncthreads();
    }
    unsigned T = prefix;

    if (t == 0) { cgt = 0; ceq = 0; }
    __syncthreads();
    for (int i = t; i < LL; i += 256) {
        unsigned u = su[i];
        if (u > T) {
            int p = atomicAdd(&cgt, 1);
            keys[p] = ((unsigned long long)u << 32) | (unsigned)(~i);
        } else if (u == T) {
            int p = atomicAdd(&ceq, 1);
            if (p < 256) eqbuf[p] = i;
        }
    }
    __syncthreads();
    if (t == 0) {
        int base = cgt;
        int ce = min(ceq, 256);
        for (int k = 0; k < need; ++k) {
            int mi = 0x7fffffff, mp = -1;
            for (int e = 0; e < ce; ++e)
                if (eqbuf[e] < mi) { mi = eqbuf[e]; mp = e; }
            keys[base + k] = ((unsigned long long)T << 32) | (unsigned)(~mi);
            eqbuf[mp] = 0x7fffffff;
        }
    }
    for (int i = t; i < 128; i += 256) if (i >= UU) keys[i] = 0ULL;
    __syncthreads();

    // bitonic sort, 128 elements, descending (=> value desc, index asc)
    for (int ksz = 2; ksz <= 128; ksz <<= 1) {
        for (int jst = ksz >> 1; jst > 0; jst >>= 1) {
            __syncthreads();
            if (t < 128) {
                int ixj = t ^ jst;
                if (ixj > t) {
                    unsigned long long a = keys[t], c = keys[ixj];
                    bool up = (t & ksz) == 0;
                    if (up ? (a < c) : (a > c)) { keys[t] = c; keys[ixj] = a; }
                }
            }
        }
    }
    __syncthreads();

    if (t < UU) {
        stop[t] = (int)(~(unsigned)(keys[t] & 0xffffffffu));
        win[t] = -1;
    }
    __syncthreads();
    if (t == 0) {
        for (int u = 0; u < UU; ++u) { int jj = min(stop[u], UU-1); win[jj] = u; }
        int n = 0;
        for (int jj = 0; jj < UU; ++jj) {
            if (win[jj] >= 0) {
                g_wl[bh*UU + n] = stop[win[jj]];
                g_wj[bh*UU + n] = jj;
                n++;
            }
        }
        g_nw[bh] = n;
    }
}

// ---------------------------------------------------------------------------
// Kernel 2: split-K attention partials for winner rows with last-split-block
// combine. SPLIT=16, CHUNK=128, 256 threads, grid (bh, UST, SPLIT).
// (Measured 18.9-19.5us across R6-R12 — verbatim.)
// ---------------------------------------------------------------------------
__global__ void k_attn(const float* __restrict__ Q, const float* __restrict__ K,
                       const float* __restrict__ V, float* __restrict__ out) {
    int bh = blockIdx.x;
    int n = g_nw[bh];
    int b = bh >> 3, h = bh & 7;
    int sp = blockIdx.z, k0 = sp * CHUNK;

    __shared__ float q[DD];
    __shared__ float p[CHUNK];
    __shared__ float red[8];
    __shared__ float ac[4][64];
    __shared__ int lastf;
    int t = threadIdx.x, lane = t & 31, warp = t >> 5;
    int grp = lane >> 3, lg = lane & 7;

    for (int u = blockIdx.y; u < n; u += UST) {
        int l = g_wl[bh*UU + u];
        if (t < DD) q[t] = Q[(((size_t)b*LL + l)*HH + h)*DD + t];
        __syncthreads();
        float4 q0 = ((float4*)q)[lg*2];
        float4 q1 = ((float4*)q)[lg*2 + 1];

        float lmax = -CUDART_INF_F;
        #pragma unroll
        for (int it = 0; it < 4; ++it) {
            int kk = warp*16 + it*4 + grp;
            const float* kr = K + (((size_t)b*LL + k0 + kk)*HH + h)*DD + lg*8;
            float4 k0v = *(const float4*)kr;
            float4 k1v = *(const float4*)(kr + 4);
            float s = q0.x*k0v.x + q0.y*k0v.y + q0.z*k0v.z + q0.w*k0v.w
                    + q1.x*k1v.x + q1.y*k1v.y + q1.z*k1v.z + q1.w*k1v.w;
            s += __shfl_xor_sync(0xffffffffu, s, 4);
            s += __shfl_xor_sync(0xffffffffu, s, 2);
            s += __shfl_xor_sync(0xffffffffu, s, 1);
            s *= 0.125f;                 // 1/sqrt(64)
            if (lg == 0) p[kk] = s;
            lmax = fmaxf(lmax, s);
        }
        lmax = fmaxf(lmax, __shfl_xor_sync(0xffffffffu, lmax, 8));
        lmax = fmaxf(lmax, __shfl_xor_sync(0xffffffffu, lmax, 16));
        if (lane == 0) red[warp] = lmax;
        __syncthreads();
        if (t == 0) { float m = red[0]; for (int w = 1; w < 8; ++w) m = fmaxf(m, red[w]); red[0] = m; }
        __syncthreads();
        float m = red[0];
        __syncthreads();

        float e = 0.f;
        if (t < CHUNK) { e = __expf(p[t] - m); p[t] = e; }
        float ls = e;
        #pragma unroll
        for (int o = 16; o; o >>= 1) ls += __shfl_xor_sync(0xffffffffu, ls, o);
        if (lane == 0) red[warp] = ls;
        __syncthreads();
        float ssumv = red[0]+red[1]+red[2]+red[3]+red[4]+red[5]+red[6]+red[7];

        int g4 = t >> 6, d = t & 63;
        float acc = 0.f;
        #pragma unroll 8
        for (int kk = g4; kk < CHUNK; kk += 4)
            acc += p[kk] * V[(((size_t)b*LL + k0 + kk)*HH + h)*DD + d];
        ac[g4][d] = acc;
        __syncthreads();
        int base = (bh*UU + u)*SPLIT + sp;
        if (t < 64)
            g_pv[(size_t)base*DD + t] = ac[0][t] + ac[1][t] + ac[2][t] + ac[3][t];
        if (t == 0) { g_pmax[base] = m; g_psum[base] = ssumv; }

        __threadfence();
        __syncthreads();
        if (t == 0) {
            int old = atomicAdd(&g_cu[bh*UU + u], 1);
            lastf = (old == SPLIT - 1);
        }
        __syncthreads();
        if (lastf) {
            if (t == 0) g_cu[bh*UU + u] = 0;   // self-reset for replay
            if (t < 64) {
                int cb = (bh*UU + u)*SPLIT;
                float mm = -CUDART_INF_F;
                #pragma unroll
                for (int i = 0; i < SPLIT; ++i) mm = fmaxf(mm, g_pmax[cb + i]);
                float s = 0.f, pv = 0.f;
                #pragma unroll
                for (int i = 0; i < SPLIT; ++i) {
                    float w = __expf(g_pmax[cb + i] - mm);
                    s  += g_psum[cb + i] * w;
                    pv += g_pv[(size_t)(cb + i)*DD + t] * w;
                }
                int j = g_wj[bh*UU + u];
                out[(((size_t)b*UU + j)*HH + h)*DD + t] = pv / s;
            }
        }
        __syncthreads();
    }
}

// ---------------------------------------------------------------------------
extern "C" void kernel_launch(void* const* d_in, const int* in_sizes, int n_in,
                              void* d_out, int out_size) {
    const float* Q   = (const float*)d_in[0];
    const float* K   = (const float*)d_in[1];
    const float* V   = (const float*)d_in[2];
    const int*   idx = (const int*)d_in[3];
    float* out = (float*)d_out;

    k_sample_topk<<<(BB*HH*LL)/8, 256>>>(Q, K, V, idx, out);
    dim3 ga(BHN, UST, SPLIT);
    k_attn<<<ga, 256>>>(Q, K, V, out);
}

// round 14
// speedup vs baseline: 2.0856x; 1.0193x over previous
#include <cuda_runtime.h>
#include <cuda_bf16.h>
#include <math_constants.h>

// Problem constants (fixed by the benchmark)
#define BB 2
#define LL 2048
#define HH 8
#define DD 64
#define UU 80
#define SS 80
#define BHN (BB*HH)
#define SPLIT 16
#define CHUNK (LL/SPLIT)      // 128 keys per split block
#define UST 8                 // u-stride for winner loop
#define NTB 16                // sample-sort buckets (j>>7 -> 32KB key tiles)

// Scratch (device globals; zero-initialized at module load)
__device__ float g_M[BB*HH*LL];           // sparsity measure M[b,h,l]
__device__ float g_vmean[BHN*DD];         // V column sums (atomic; reset by k_topk)
__device__ int   g_cu[BHN*UU];            // per-(bh,u) split counter (self-reset)
__device__ int   g_nw[BHN];               // winners per (b,h)
__device__ int   g_wl[BHN*UU];            // winner: source token l
__device__ int   g_wj[BHN*UU];            // winner: output slot j
__device__ float g_pmax[BHN*UU*SPLIT];    // split-softmax partial max
__device__ float g_psum[BHN*UU*SPLIT];    // split-softmax partial sum(exp)
__device__ float g_pv  [BHN*UU*SPLIT*DD]; // split partial (unnormalized) PV

// ---------------------------------------------------------------------------
// Kernel 1: sampled scores -> M[b,h,l] + V column sums. SMALL smem (~3.8KB)
// so 8 CTAs/SM leave ~198KB of L1 for K-row reuse. Each warp counting-sorts
// its 80 sample indices into 16 buckets by 32KB key tile (j>>7) and gathers
// in tile order; co-resident same-bh CTAs walk tiles in the same order so
// the hot set (2 bh x 2-3 tiles = 128-192KB) fits L1. Gather inner loop is
// the R5-validated shape: 4 independent 256B LDG gathers per warp-iteration.
// ---------------------------------------------------------------------------
__global__ void k_sample(const float* __restrict__ Q, const float* __restrict__ K,
                         const float* __restrict__ V, const int* __restrict__ idx) {
    __shared__ float sv[8][64];
    __shared__ unsigned short sjb[8][SS];   // per-warp tile-sorted sample indices
    __shared__ int scn[8][NTB];             // per-warp per-tile counters

    int t = threadIdx.x, lane = t & 31, warp = t >> 5;
    int gw = blockIdx.x * 8 + warp;
    int l  = gw & (LL-1);
    int bh = gw >> 11;
    int b = bh >> 3, h = bh & 7;
    int grp = lane >> 3, lg = lane & 7;

    const float* qrow = Q + (((size_t)b*LL + l)*HH + h)*DD;
    float4 q0 = *(const float4*)(qrow + lg*8);
    float4 q1 = *(const float4*)(qrow + lg*8 + 4);

    // V row for this l (coalesced float2 per lane)
    float2 vv = *(const float2*)(V + (((size_t)b*LL + l)*HH + h)*DD + lane*2);
    sv[warp][lane*2] = vv.x; sv[warp][lane*2+1] = vv.y;

    // ---- warp-local counting sort of 80 sample indices into 16 tile buckets
    const int* irow = idx + l*SS;
    int j0 = irow[lane];
    int j1 = irow[lane + 32];
    int j2 = (lane < 16) ? irow[lane + 64] : 0;
    if (lane < NTB) scn[warp][lane] = 0;
    __syncwarp();
    atomicAdd(&scn[warp][j0 >> 7], 1);
    atomicAdd(&scn[warp][j1 >> 7], 1);
    if (lane < 16) atomicAdd(&scn[warp][j2 >> 7], 1);
    __syncwarp();
    if (lane < NTB) {
        int c = scn[warp][lane];
        int pre = c;
        #pragma unroll
        for (int o = 1; o < NTB; o <<= 1) {
            int v = __shfl_up_sync(0x0000ffffu, pre, o);
            if (lane >= o) pre += v;
        }
        scn[warp][lane] = pre - c;       // exclusive start per tile
    }
    __syncwarp();
    { int p = atomicAdd(&scn[warp][j0 >> 7], 1); sjb[warp][p] = (unsigned short)j0; }
    { int p = atomicAdd(&scn[warp][j1 >> 7], 1); sjb[warp][p] = (unsigned short)j1; }
    if (lane < 16) { int p = atomicAdd(&scn[warp][j2 >> 7], 1); sjb[warp][p] = (unsigned short)j2; }
    __syncwarp();

    // ---- gather loop (R5 shape; indices tile-sorted) ----
    float vmax = -CUDART_INF_F, vsum = 0.f;
    #pragma unroll 5
    for (int it = 0; it < SS/4; ++it) {
        int j = sjb[warp][it*4 + grp];
        const float* krow = K + (((size_t)b*LL + j)*HH + h)*DD + lg*8;
        float4 k0 = *(const float4*)(krow);
        float4 k1 = *(const float4*)(krow + 4);
        float p = q0.x*k0.x + q0.y*k0.y + q0.z*k0.z + q0.w*k0.w
                + q1.x*k1.x + q1.y*k1.y + q1.z*k1.z + q1.w*k1.w;
        p += __shfl_xor_sync(0xffffffffu, p, 4);
        p += __shfl_xor_sync(0xffffffffu, p, 2);
        p += __shfl_xor_sync(0xffffffffu, p, 1);
        vmax = fmaxf(vmax, p);
        vsum += p;
    }
    vmax = fmaxf(vmax, __shfl_xor_sync(0xffffffffu, vmax, 8));
    vmax = fmaxf(vmax, __shfl_xor_sync(0xffffffffu, vmax, 16));
    vsum += __shfl_xor_sync(0xffffffffu, vsum, 8);
    vsum += __shfl_xor_sync(0xffffffffu, vsum, 16);
    if (lane == 0) g_M[gw] = vmax - vsum * (1.0f/(float)LL);

    __syncthreads();
    if (t < 64) {
        float s = sv[0][t] + sv[1][t] + sv[2][t] + sv[3][t]
                + sv[4][t] + sv[5][t] + sv[6][t] + sv[7][t];
        atomicAdd(&g_vmean[bh*64 + t], s);
    }
}

// ---------------------------------------------------------------------------
// Kernel 2: per-(b,h) top-80 (radix select + bitonic, exact jax.lax.top_k
// semantics), winner replay, V_mean broadcast fill. (R13-validated body.)
// ---------------------------------------------------------------------------
__global__ void k_topk(float* __restrict__ out) {
    int bh = blockIdx.x, t = threadIdx.x, lane = t & 31;
    int b = bh >> 3, h = bh & 7;
    __shared__ unsigned su[LL];
    __shared__ int hist[256];
    __shared__ int scnt[2];
    __shared__ unsigned long long keys[128];
    __shared__ int eqbuf[256];
    __shared__ int cgt, ceq;
    __shared__ int stop[UU];
    __shared__ int win[UU];
    __shared__ float mean[64];

    if (t < 64) {
        mean[t] = g_vmean[bh*64 + t] * (1.0f/(float)LL);
        g_vmean[bh*64 + t] = 0.f;           // reset for next graph replay
    }
    for (int i = t; i < LL; i += 256) {
        unsigned bb = __float_as_uint(g_M[bh*LL + i]);
        su[i] = (bb & 0x80000000u) ? ~bb : (bb | 0x80000000u);
    }
    __syncthreads();

    // broadcast-fill all 80 output rows with V_mean (winners overwritten later)
    for (int e = t; e < UU*64; e += 256) {
        int j = e >> 6, d = e & 63;
        out[(((size_t)b*UU + j)*HH + h)*DD + d] = mean[d];
    }

    // 4-pass byte radix: T = 80th-largest transformed value
    unsigned prefix = 0, prefmask = 0;
    int need = UU;
    for (int pass = 0; pass < 4; ++pass) {
        int shift = 24 - pass*8;
        hist[t] = 0;
        __syncthreads();
        for (int i = t; i < LL; i += 256) {
            unsigned u = su[i];
            if ((u & prefmask) == prefix) atomicAdd(&hist[(u >> shift) & 0xFF], 1);
        }
        __syncthreads();
        if (t < 32) {
            int base = 255 - t*8;
            int s = 0;
            #pragma unroll
            for (int e = 0; e < 8; ++e) s += hist[base - e];
            int pre = s;
            #pragma unroll
            for (int o = 1; o < 32; o <<= 1) {
                int v = __shfl_up_sync(0xffffffffu, pre, o);
                if (lane >= o) pre += v;
            }
            int excl = pre - s;
            if (excl < need && need <= pre) {
                int acc = excl;
                #pragma unroll
                for (int e = 0; e < 8; ++e) {
                    int hb = hist[base - e];
                    if (acc + hb >= need) { scnt[0] = base - e; scnt[1] = acc; break; }
                    acc += hb;
                }
            }
        }
        __syncthreads();
        prefix |= ((unsigned)scnt[0]) << shift;
        prefmask |= 0xFFu << shift;
        need -= scnt[1];
        __syncthreads();
    }
    unsigned T = prefix;

    if (t == 0) { cgt = 0; ceq = 0; }
    __syncthreads();
    for (int i = t; i < LL; i += 256) {
        unsigned u = su[i];
        if (u > T) {
            int p = atomicAdd(&cgt, 1);
            keys[p] = ((unsigned long long)u << 32) | (unsigned)(~i);
        } else if (u == T) {
            int p = atomicAdd(&ceq, 1);
            if (p < 256) eqbuf[p] = i;
        }
    }
    __syncthreads();
    if (t == 0) {
        int base = cgt;
        int ce = min(ceq, 256);
        for (int k = 0; k < need; ++k) {
            int mi = 0x7fffffff, mp = -1;
            for (int e = 0; e < ce; ++e)
                if (eqbuf[e] < mi) { mi = eqbuf[e]; mp = e; }
            keys[base + k] = ((unsigned long long)T << 32) | (unsigned)(~mi);
            eqbuf[mp] = 0x7fffffff;
        }
    }
    for (int i = t; i < 128; i += 256) if (i >= UU) keys[i] = 0ULL;
    __syncthreads();

    // bitonic sort, 128 elements, descending (=> value desc, index asc)
    for (int ksz = 2; ksz <= 128; ksz <<= 1) {
        for (int jst = ksz >> 1; jst > 0; jst >>= 1) {
            __syncthreads();
            if (t < 128) {
                int ixj = t ^ jst;
                if (ixj > t) {
                    unsigned long long a = keys[t], c = keys[ixj];
                    bool up = (t & ksz) == 0;
                    if (up ? (a < c) : (a > c)) { keys[t] = c; keys[ixj] = a; }
                }
            }
        }
    }
    __syncthreads();

    if (t < UU) {
        stop[t] = (int)(~(unsigned)(keys[t] & 0xffffffffu));
        win[t] = -1;
    }
    __syncthreads();
    if (t == 0) {
        for (int u = 0; u < UU; ++u) { int jj = min(stop[u], UU-1); win[jj] = u; }
        int n = 0;
        for (int jj = 0; jj < UU; ++jj) {
            if (win[jj] >= 0) {
                g_wl[bh*UU + n] = stop[win[jj]];
                g_wj[bh*UU + n] = jj;
                n++;
            }
        }
        g_nw[bh] = n;
    }
}

// ---------------------------------------------------------------------------
// Kernel 3: split-K attention partials for winner rows with last-split-block
// combine. SPLIT=16, CHUNK=128, 256 threads, grid (bh, UST, SPLIT).
// (Measured 18.8-19.5us across R6-R13 — verbatim.)
// ---------------------------------------------------------------------------
__global__ void k_attn(const float* __restrict__ Q, const float* __restrict__ K,
                       const float* __restrict__ V, float* __restrict__ out) {
    int bh = blockIdx.x;
    int n = g_nw[bh];
    int b = bh >> 3, h = bh & 7;
    int sp = blockIdx.z, k0 = sp * CHUNK;

    __shared__ float q[DD];
    __shared__ float p[CHUNK];
    __shared__ float red[8];
    __shared__ float ac[4][64];
    __shared__ int lastf;
    int t = threadIdx.x, lane = t & 31, warp = t >> 5;
    int grp = lane >> 3, lg = lane & 7;

    for (int u = blockIdx.y; u < n; u += UST) {
        int l = g_wl[bh*UU + u];
        if (t < DD) q[t] = Q[(((size_t)b*LL + l)*HH + h)*DD + t];
        __syncthreads();
        float4 q0 = ((float4*)q)[lg*2];
        float4 q1 = ((float4*)q)[lg*2 + 1];

        float lmax = -CUDART_INF_F;
        #pragma unroll
        for (int it = 0; it < 4; ++it) {
            int kk = warp*16 + it*4 + grp;
            const float* kr = K + (((size_t)b*LL + k0 + kk)*HH + h)*DD + lg*8;
            float4 k0v = *(const float4*)kr;
            float4 k1v = *(const float4*)(kr + 4);
            float s = q0.x*k0v.x + q0.y*k0v.y + q0.z*k0v.z + q0.w*k0v.w
                    + q1.x*k1v.x + q1.y*k1v.y + q1.z*k1v.z + q1.w*k1v.w;
            s += __shfl_xor_sync(0xffffffffu, s, 4);
            s += __shfl_xor_sync(0xffffffffu, s, 2);
            s += __shfl_xor_sync(0xffffffffu, s, 1);
            s *= 0.125f;                 // 1/sqrt(64)
            if (lg == 0) p[kk] = s;
            lmax = fmaxf(lmax, s);
        }
        lmax = fmaxf(lmax, __shfl_xor_sync(0xffffffffu, lmax, 8));
        lmax = fmaxf(lmax, __shfl_xor_sync(0xffffffffu, lmax, 16));
        if (lane == 0) red[warp] = lmax;
        __syncthreads();
        if (t == 0) { float m = red[0]; for (int w = 1; w < 8; ++w) m = fmaxf(m, red[w]); red[0] = m; }
        __syncthreads();
        float m = red[0];
        __syncthreads();

        float e = 0.f;
        if (t < CHUNK) { e = __expf(p[t] - m); p[t] = e; }
        float ls = e;
        #pragma unroll
        for (int o = 16; o; o >>= 1) ls += __shfl_xor_sync(0xffffffffu, ls, o);
        if (lane == 0) red[warp] = ls;
        __syncthreads();
        float ssumv = red[0]+red[1]+red[2]+red[3]+red[4]+red[5]+red[6]+red[7];

        int g4 = t >> 6, d = t & 63;
        float acc = 0.f;
        #pragma unroll 8
        for (int kk = g4; kk < CHUNK; kk += 4)
            acc += p[kk] * V[(((size_t)b*LL + k0 + kk)*HH + h)*DD + d];
        ac[g4][d] = acc;
        __syncthreads();
        int base = (bh*UU + u)*SPLIT + sp;
        if (t < 64)
            g_pv[(size_t)base*DD + t] = ac[0][t] + ac[1][t] + ac[2][t] + ac[3][t];
        if (t == 0) { g_pmax[base] = m; g_psum[base] = ssumv; }

        __threadfence();
        __syncthreads();
        if (t == 0) {
            int old = atomicAdd(&g_cu[bh*UU + u], 1);
            lastf = (old == SPLIT - 1);
        }
        __syncthreads();
        if (lastf) {
            if (t == 0) g_cu[bh*UU + u] = 0;   // self-reset for replay
            if (t < 64) {
                int cb = (bh*UU + u)*SPLIT;
                float mm = -CUDART_INF_F;
                #pragma unroll
                for (int i = 0; i < SPLIT; ++i) mm = fmaxf(mm, g_pmax[cb + i]);
                float s = 0.f, pv = 0.f;
                #pragma unroll
                for (int i = 0; i < SPLIT; ++i) {
                    float w = __expf(g_pmax[cb + i] - mm);
                    s  += g_psum[cb + i] * w;
                    pv += g_pv[(size_t)(cb + i)*DD + t] * w;
                }
                int j = g_wj[bh*UU + u];
                out[(((size_t)b*UU + j)*HH + h)*DD + t] = pv / s;
            }
        }
        __syncthreads();
    }
}

// ---------------------------------------------------------------------------
extern "C" void kernel_launch(void* const* d_in, const int* in_sizes, int n_in,
                              void* d_out, int out_size) {
    const float* Q   = (const float*)d_in[0];
    const float* K   = (const float*)d_in[1];
    const float* V   = (const float*)d_in[2];
    const int*   idx = (const int*)d_in[3];
    float* out = (float*)d_out;

    k_sample<<<(BB*HH*LL)/8, 256>>>(Q, K, V, idx);
    k_topk<<<BHN, 256>>>(out);
    dim3 ga(BHN, UST, SPLIT);
    k_attn<<<ga, 256>>>(Q, K, V, out);
}